// round 2
// baseline (speedup 1.0000x reference)
#include <cuda_runtime.h>

#define T_STEPS 2048
#define BATCH   256
#define DIN     128
#define NG      16      // 4 gates * 4 units, k = gate*4 + unit

// Scratch: x-part projections (+bias+theta folded), layout [t][b][16]
__device__ float g_xproj[T_STEPS * BATCH * NG];

// ---------------------------------------------------------------------------
// Kernel 1: fused 4-gate projection  xproj[t,b,k] = x[t,b,:] @ Wx[:,k] + b[k] + theta[k]
// ---------------------------------------------------------------------------
#define TILE_ROWS    64
#define PROJ_THREADS 256

__global__ __launch_bounds__(PROJ_THREADS)
void proj_kernel(const float* __restrict__ x,
                 const float* __restrict__ Wf, const float* __restrict__ bf, const float* __restrict__ thf,
                 const float* __restrict__ Wi, const float* __restrict__ bi, const float* __restrict__ thi,
                 const float* __restrict__ Wu, const float* __restrict__ bu, const float* __restrict__ thu,
                 const float* __restrict__ Wo, const float* __restrict__ bo, const float* __restrict__ tho)
{
    __shared__ float xs[TILE_ROWS][132];   // stride 132 -> conflict-free float4 LDS
    __shared__ float ws[DIN][NG];
    __shared__ float bt[NG];

    const int tid = threadIdx.x;
    const long rowBase = (long)blockIdx.x * TILE_ROWS;

    // coalesced load of x tile
    const float4* x4 = (const float4*)x + rowBase * (DIN / 4);
    #pragma unroll
    for (int i = tid; i < TILE_ROWS * (DIN / 4); i += PROJ_THREADS) {
        float4 v = x4[i];
        int row = i >> 5;        // DIN/4 == 32
        int c4  = i & 31;
        *(float4*)&xs[row][c4 * 4] = v;
    }
    // stage W: ws[j][k], j = input feature, k = gate*4+unit
    for (int i = tid; i < DIN * NG; i += PROJ_THREADS) {
        int j = i >> 4, k = i & 15;
        int g = k >> 2, u = k & 3;
        const float* W = (g == 0) ? Wf : (g == 1) ? Wi : (g == 2) ? Wu : Wo;
        ws[j][k] = W[j * 4 + u];
    }
    if (tid < NG) {
        int g = tid >> 2, u = tid & 3;
        const float* b  = (g == 0) ? bf  : (g == 1) ? bi  : (g == 2) ? bu  : bo;
        const float* th = (g == 0) ? thf : (g == 1) ? thi : (g == 2) ? thu : tho;
        bt[tid] = b[u] + th[u];
    }
    __syncthreads();

    const int r  = tid & (TILE_ROWS - 1);  // row within tile
    const int kg = tid >> 6;               // 0..3 -> output cols kg*4..kg*4+3
    float a0 = 0.f, a1 = 0.f, a2 = 0.f, a3 = 0.f;

    #pragma unroll
    for (int jj = 0; jj < DIN / 4; jj++) {
        float4 xv = *(const float4*)&xs[r][jj * 4];
        float4 w0 = *(const float4*)&ws[jj * 4 + 0][kg * 4];
        float4 w1 = *(const float4*)&ws[jj * 4 + 1][kg * 4];
        float4 w2 = *(const float4*)&ws[jj * 4 + 2][kg * 4];
        float4 w3 = *(const float4*)&ws[jj * 4 + 3][kg * 4];
        a0 = fmaf(xv.x, w0.x, fmaf(xv.y, w1.x, fmaf(xv.z, w2.x, fmaf(xv.w, w3.x, a0))));
        a1 = fmaf(xv.x, w0.y, fmaf(xv.y, w1.y, fmaf(xv.z, w2.y, fmaf(xv.w, w3.y, a1))));
        a2 = fmaf(xv.x, w0.z, fmaf(xv.y, w1.z, fmaf(xv.z, w2.z, fmaf(xv.w, w3.z, a2))));
        a3 = fmaf(xv.x, w0.w, fmaf(xv.y, w1.w, fmaf(xv.z, w2.w, fmaf(xv.w, w3.w, a3))));
    }
    float4 o;
    o.x = a0 + bt[kg * 4 + 0];
    o.y = a1 + bt[kg * 4 + 1];
    o.z = a2 + bt[kg * 4 + 2];
    o.w = a3 + bt[kg * 4 + 3];
    *(float4*)&g_xproj[(rowBase + r) * NG + kg * 4] = o;
}

// ---------------------------------------------------------------------------
// Kernel 2: sequential recurrence, 1 thread per batch element
// ---------------------------------------------------------------------------
// sigmoid on [-1,1] via odd Taylor poly (err <= ~3e-6) -- keeps the MUFU pipe free
__device__ __forceinline__ float sigp(float xv) {
    float x2 = xv * xv;
    float t = fmaf(x2, 2.135765e-5f, -2.1081349e-4f);
    t = fmaf(x2, t, 2.0833333e-3f);
    t = fmaf(x2, t, -2.0833333e-2f);
    t = fmaf(x2, t, 0.25f);
    return fmaf(xv, t, 0.5f);
}
// accurate-enough tanh via exp2 (rel err ~1e-6), bounded args
__device__ __forceinline__ float tanh_e(float xv) {
    float e = __expf(xv + xv);                 // e^{2x}
    return 1.0f - 2.0f * __fdividef(1.0f, e + 1.0f);
}

#define DEPTH 4

__global__ __launch_bounds__(32)
void recur_kernel(const float* __restrict__ Wf, const float* __restrict__ Wi,
                  const float* __restrict__ Wu, const float* __restrict__ Wo,
                  float* __restrict__ out)
{
    const int b = blockIdx.x * 32 + threadIdx.x;

    // hidden-part weights Wh[m][k] = W_gate[128+m][unit]  (uniform across threads)
    float Wh[4][16];
    #pragma unroll
    for (int m = 0; m < 4; m++) {
        #pragma unroll
        for (int u = 0; u < 4; u++) {
            Wh[m][0 * 4 + u] = Wf[(128 + m) * 4 + u];
            Wh[m][1 * 4 + u] = Wi[(128 + m) * 4 + u];
            Wh[m][2 * 4 + u] = Wu[(128 + m) * 4 + u];
            Wh[m][3 * 4 + u] = Wo[(128 + m) * 4 + u];
        }
    }

    float h0 = 0.f, h1 = 0.f, h2 = 0.f, h3 = 0.f;
    float c0 = 0.f, c1 = 0.f, c2 = 0.f, c3 = 0.f;

    const float4* xp = (const float4*)g_xproj + (size_t)b * 4;  // per-t stride: BATCH*4 float4
    float4 buf[DEPTH][4];
    #pragma unroll
    for (int d = 0; d < DEPTH; d++) {
        #pragma unroll
        for (int q = 0; q < 4; q++)
            buf[d][q] = xp[(size_t)d * (BATCH * 4) + q];
    }

    float4* outv = (float4*)out;

    #pragma unroll 4
    for (int t = 0; t < T_STEPS; t++) {
        const int slot = t & (DEPTH - 1);
        float zx[16];
        *(float4*)&zx[0]  = buf[slot][0];
        *(float4*)&zx[4]  = buf[slot][1];
        *(float4*)&zx[8]  = buf[slot][2];
        *(float4*)&zx[12] = buf[slot][3];

        if (t + DEPTH < T_STEPS) {
            #pragma unroll
            for (int q = 0; q < 4; q++)
                buf[slot][q] = xp[(size_t)(t + DEPTH) * (BATCH * 4) + q];
        }

        // z_k = xproj_k + h . Wh[:,k]  (theta+bias already folded in), then cos
        float p[16];
        #pragma unroll
        for (int k = 0; k < 16; k++) {
            float z = fmaf(h0, Wh[0][k],
                      fmaf(h1, Wh[1][k],
                      fmaf(h2, Wh[2][k],
                      fmaf(h3, Wh[3][k], zx[k]))));
            p[k] = __cosf(z);
        }

        // cumprod within each gate (tree form, depth 2)
        #pragma unroll
        for (int g = 0; g < 4; g++) {
            float q0  = p[g * 4 + 0];
            float q01 = q0 * p[g * 4 + 1];
            float q23 = p[g * 4 + 2] * p[g * 4 + 3];
            p[g * 4 + 1] = q01;
            p[g * 4 + 2] = q01 * p[g * 4 + 2];
            p[g * 4 + 3] = q01 * q23;
        }

        float f0 = sigp(p[0]),  f1 = sigp(p[1]),  f2 = sigp(p[2]),  f3 = sigp(p[3]);
        float i0 = sigp(p[4]),  i1 = sigp(p[5]),  i2 = sigp(p[6]),  i3 = sigp(p[7]);
        float g0 = tanh_e(p[8]), g1 = tanh_e(p[9]), g2 = tanh_e(p[10]), g3 = tanh_e(p[11]);
        float o0 = sigp(p[12]), o1 = sigp(p[13]), o2 = sigp(p[14]), o3 = sigp(p[15]);

        c0 = fmaf(f0, c0, i0 * g0);
        c1 = fmaf(f1, c1, i1 * g1);
        c2 = fmaf(f2, c2, i2 * g2);
        c3 = fmaf(f3, c3, i3 * g3);

        h0 = o0 * tanh_e(c0);
        h1 = o1 * tanh_e(c1);
        h2 = o2 * tanh_e(c2);
        h3 = o3 * tanh_e(c3);

        float4 hv; hv.x = h0; hv.y = h1; hv.z = h2; hv.w = h3;
        outv[(size_t)t * BATCH + b] = hv;
    }

    // hx, cx appended after outputs
    float4 hv; hv.x = h0; hv.y = h1; hv.z = h2; hv.w = h3;
    float4 cv; cv.x = c0; cv.y = c1; cv.z = c2; cv.w = c3;
    outv[(size_t)T_STEPS * BATCH + b]         = hv;
    outv[(size_t)T_STEPS * BATCH + BATCH + b] = cv;
}

// ---------------------------------------------------------------------------
extern "C" void kernel_launch(void* const* d_in, const int* in_sizes, int n_in,
                              void* d_out, int out_size)
{
    (void)in_sizes; (void)n_in; (void)out_size;
    const float* x   = (const float*)d_in[0];
    const float* Wf  = (const float*)d_in[1];
    const float* bf  = (const float*)d_in[2];
    const float* thf = (const float*)d_in[3];
    const float* Wi  = (const float*)d_in[4];
    const float* bi  = (const float*)d_in[5];
    const float* thi = (const float*)d_in[6];
    const float* Wu  = (const float*)d_in[7];
    const float* bu  = (const float*)d_in[8];
    const float* thu = (const float*)d_in[9];
    const float* Wo  = (const float*)d_in[10];
    const float* bo  = (const float*)d_in[11];
    const float* tho = (const float*)d_in[12];
    float* out = (float*)d_out;

    proj_kernel<<<(T_STEPS * BATCH) / TILE_ROWS, PROJ_THREADS>>>(
        x, Wf, bf, thf, Wi, bi, thi, Wu, bu, thu, Wo, bo, tho);
    recur_kernel<<<BATCH / 32, 32>>>(Wf, Wi, Wu, Wo, out);
}

// round 3
// speedup vs baseline: 1.4144x; 1.4144x over previous
#include <cuda_runtime.h>

#define T_STEPS 2048
#define BATCH   256
#define DIN     128
#define NG      16      // 4 gates * 4 units; scratch layout k = u*4 + g
#define RDEPTH  4

// Scratch: x-part projections (+bias+theta folded), layout [t][b][u*4+g]
// Over-allocated by RDEPTH steps so the recurrence prefetch needs no bounds check.
__device__ float g_xproj[(T_STEPS + RDEPTH) * BATCH * NG];

// ---------------------------------------------------------------------------
// Kernel 1: fused 4-gate projection  xproj[t,b,u*4+g] = x[t,b,:] @ Wg[:, u] + b_g[u] + theta_g[u]
// ---------------------------------------------------------------------------
#define TILE_ROWS    64
#define PROJ_THREADS 256

__global__ __launch_bounds__(PROJ_THREADS)
void proj_kernel(const float* __restrict__ x,
                 const float* __restrict__ Wf, const float* __restrict__ bf, const float* __restrict__ thf,
                 const float* __restrict__ Wi, const float* __restrict__ bi, const float* __restrict__ thi,
                 const float* __restrict__ Wu, const float* __restrict__ bu, const float* __restrict__ thu,
                 const float* __restrict__ Wo, const float* __restrict__ bo, const float* __restrict__ tho)
{
    __shared__ float xs[TILE_ROWS][132];   // stride 132 -> conflict-free float4 LDS
    __shared__ float ws[DIN][NG];          // ws[j][u*4+g]
    __shared__ float bt[NG];

    const int tid = threadIdx.x;
    const long rowBase = (long)blockIdx.x * TILE_ROWS;

    // coalesced load of x tile
    const float4* x4 = (const float4*)x + rowBase * (DIN / 4);
    #pragma unroll
    for (int i = tid; i < TILE_ROWS * (DIN / 4); i += PROJ_THREADS) {
        float4 v = x4[i];
        int row = i >> 5;        // DIN/4 == 32
        int c4  = i & 31;
        *(float4*)&xs[row][c4 * 4] = v;
    }
    // stage W transposed: k = u*4 + g
    for (int i = tid; i < DIN * NG; i += PROJ_THREADS) {
        int j = i >> 4, k = i & 15;
        int u = k >> 2, g = k & 3;
        const float* W = (g == 0) ? Wf : (g == 1) ? Wi : (g == 2) ? Wu : Wo;
        ws[j][k] = W[j * 4 + u];
    }
    if (tid < NG) {
        int u = tid >> 2, g = tid & 3;
        const float* b  = (g == 0) ? bf  : (g == 1) ? bi  : (g == 2) ? bu  : bo;
        const float* th = (g == 0) ? thf : (g == 1) ? thi : (g == 2) ? thu : tho;
        bt[tid] = b[u] + th[u];
    }
    __syncthreads();

    const int r  = tid & (TILE_ROWS - 1);  // row within tile
    const int kg = tid >> 6;               // 0..3 -> output cols kg*4..kg*4+3
    float a0 = 0.f, a1 = 0.f, a2 = 0.f, a3 = 0.f;

    #pragma unroll
    for (int jj = 0; jj < DIN / 4; jj++) {
        float4 xv = *(const float4*)&xs[r][jj * 4];
        float4 w0 = *(const float4*)&ws[jj * 4 + 0][kg * 4];
        float4 w1 = *(const float4*)&ws[jj * 4 + 1][kg * 4];
        float4 w2 = *(const float4*)&ws[jj * 4 + 2][kg * 4];
        float4 w3 = *(const float4*)&ws[jj * 4 + 3][kg * 4];
        a0 = fmaf(xv.x, w0.x, fmaf(xv.y, w1.x, fmaf(xv.z, w2.x, fmaf(xv.w, w3.x, a0))));
        a1 = fmaf(xv.x, w0.y, fmaf(xv.y, w1.y, fmaf(xv.z, w2.y, fmaf(xv.w, w3.y, a1))));
        a2 = fmaf(xv.x, w0.z, fmaf(xv.y, w1.z, fmaf(xv.z, w2.z, fmaf(xv.w, w3.z, a2))));
        a3 = fmaf(xv.x, w0.w, fmaf(xv.y, w1.w, fmaf(xv.z, w2.w, fmaf(xv.w, w3.w, a3))));
    }
    float4 o;
    o.x = a0 + bt[kg * 4 + 0];
    o.y = a1 + bt[kg * 4 + 1];
    o.z = a2 + bt[kg * 4 + 2];
    o.w = a3 + bt[kg * 4 + 3];
    *(float4*)&g_xproj[(rowBase + r) * NG + kg * 4] = o;
}

// ---------------------------------------------------------------------------
// Kernel 2: recurrence; 4 lanes per batch element (lane owns hidden unit u)
// ---------------------------------------------------------------------------
// sigmoid on [-1,1] via odd Taylor poly (err <= ~3e-6) -- FMA pipe only
__device__ __forceinline__ float sigp(float xv) {
    float x2 = xv * xv;
    float t = fmaf(x2, 2.135765e-5f, -2.1081349e-4f);
    t = fmaf(x2, t, 2.0833333e-3f);
    t = fmaf(x2, t, -2.0833333e-2f);
    t = fmaf(x2, t, 0.25f);
    return fmaf(xv, t, 0.5f);
}
// tanh via exp2 (rel err ~1e-6), args bounded (|x| <= ~2.1)
__device__ __forceinline__ float tanh_e(float xv) {
    float e = __expf(xv + xv);                 // e^{2x}
    return 1.0f - 2.0f * __fdividef(1.0f, e + 1.0f);
}

__global__ __launch_bounds__(32)
void recur_kernel(const float* __restrict__ Wf, const float* __restrict__ Wi,
                  const float* __restrict__ Wu, const float* __restrict__ Wo,
                  float* __restrict__ out)
{
    const int lane = threadIdx.x;
    const int u    = lane & 3;                       // hidden unit owned by this lane
    const int b    = blockIdx.x * 8 + (lane >> 2);   // batch element of this 4-lane group

    // Whl[m][g] = W_gate_g[(128+m)*4 + u] : weight from hidden unit m into (gate g, unit u)
    float Whl[4][4];
    #pragma unroll
    for (int m = 0; m < 4; m++) {
        Whl[m][0] = Wf[(128 + m) * 4 + u];
        Whl[m][1] = Wi[(128 + m) * 4 + u];
        Whl[m][2] = Wu[(128 + m) * 4 + u];
        Whl[m][3] = Wo[(128 + m) * 4 + u];
    }

    float h0 = 0.f, h1 = 0.f, h2 = 0.f, h3 = 0.f;   // full hidden state (broadcast each step)
    float c  = 0.f;                                  // this lane's cell unit

    // xproj stream: lane reads float4 {g=0..3} for its (b, u); coalesced 512B/warp/step
    const float4* xp = (const float4*)g_xproj + ((size_t)b * 4 + u);
    float4 buf[RDEPTH];
    #pragma unroll
    for (int d = 0; d < RDEPTH; d++)
        buf[d] = xp[(size_t)d * (BATCH * 4)];

    #pragma unroll 4
    for (int t = 0; t < T_STEPS; t++) {
        const int slot = t & (RDEPTH - 1);
        float4 zx = buf[slot];
        buf[slot] = xp[(size_t)(t + RDEPTH) * (BATCH * 4)];  // over-allocated: no bound check

        // z_g = zx_g + sum_m h_m * Whl[m][g], then cos
        float q0 = __cosf(fmaf(h0, Whl[0][0], fmaf(h1, Whl[1][0], fmaf(h2, Whl[2][0], fmaf(h3, Whl[3][0], zx.x)))));
        float q1 = __cosf(fmaf(h0, Whl[0][1], fmaf(h1, Whl[1][1], fmaf(h2, Whl[2][1], fmaf(h3, Whl[3][1], zx.y)))));
        float q2 = __cosf(fmaf(h0, Whl[0][2], fmaf(h1, Whl[1][2], fmaf(h2, Whl[2][2], fmaf(h3, Whl[3][2], zx.z)))));
        float q3 = __cosf(fmaf(h0, Whl[0][3], fmaf(h1, Whl[1][3], fmaf(h2, Whl[2][3], fmaf(h3, Whl[3][3], zx.w)))));

        // inclusive cumprod across the 4 lanes of the group (over units), per gate
        {
            float v0 = __shfl_up_sync(0xffffffffu, q0, 1, 4);
            float v1 = __shfl_up_sync(0xffffffffu, q1, 1, 4);
            float v2 = __shfl_up_sync(0xffffffffu, q2, 1, 4);
            float v3 = __shfl_up_sync(0xffffffffu, q3, 1, 4);
            if (u >= 1) { q0 *= v0; q1 *= v1; q2 *= v2; q3 *= v3; }
            v0 = __shfl_up_sync(0xffffffffu, q0, 2, 4);
            v1 = __shfl_up_sync(0xffffffffu, q1, 2, 4);
            v2 = __shfl_up_sync(0xffffffffu, q2, 2, 4);
            v3 = __shfl_up_sync(0xffffffffu, q3, 2, 4);
            if (u >= 2) { q0 *= v0; q1 *= v1; q2 *= v2; q3 *= v3; }
        }

        // activations + state update, all local to this lane's unit
        float f  = sigp(q0);
        float i  = sigp(q1);
        float gg = tanh_e(q2);
        float o  = sigp(q3);

        c = fmaf(f, c, i * gg);
        float hu = o * tanh_e(c);

        out[((size_t)t * BATCH + b) * 4 + u] = hu;   // 128B coalesced per warp

        // broadcast h within the 4-lane group for the next step's z
        h0 = __shfl_sync(0xffffffffu, hu, 0, 4);
        h1 = __shfl_sync(0xffffffffu, hu, 1, 4);
        h2 = __shfl_sync(0xffffffffu, hu, 2, 4);
        h3 = __shfl_sync(0xffffffffu, hu, 3, 4);
    }

    // hx, cx appended after outputs
    out[(size_t)T_STEPS * BATCH * 4 + (size_t)b * 4 + u]                 = h0 * (u == 0) + h1 * (u == 1) + h2 * (u == 2) + h3 * (u == 3);
    out[(size_t)T_STEPS * BATCH * 4 + (size_t)BATCH * 4 + (size_t)b * 4 + u] = c;
}

// ---------------------------------------------------------------------------
extern "C" void kernel_launch(void* const* d_in, const int* in_sizes, int n_in,
                              void* d_out, int out_size)
{
    (void)in_sizes; (void)n_in; (void)out_size;
    const float* x   = (const float*)d_in[0];
    const float* Wf  = (const float*)d_in[1];
    const float* bf  = (const float*)d_in[2];
    const float* thf = (const float*)d_in[3];
    const float* Wi  = (const float*)d_in[4];
    const float* bi  = (const float*)d_in[5];
    const float* thi = (const float*)d_in[6];
    const float* Wu  = (const float*)d_in[7];
    const float* bu  = (const float*)d_in[8];
    const float* thu = (const float*)d_in[9];
    const float* Wo  = (const float*)d_in[10];
    const float* bo  = (const float*)d_in[11];
    const float* tho = (const float*)d_in[12];
    float* out = (float*)d_out;

    proj_kernel<<<(T_STEPS * BATCH) / TILE_ROWS, PROJ_THREADS>>>(
        x, Wf, bf, thf, Wi, bi, thi, Wu, bu, thu, Wo, bo, tho);
    recur_kernel<<<BATCH / 8, 32>>>(Wf, Wi, Wu, Wo, out);
}

// round 4
// speedup vs baseline: 1.4876x; 1.0517x over previous
#include <cuda_runtime.h>

#define T_STEPS 2048
#define BATCH   256
#define DIN     128
#define NG      16      // 4 gates * 4 units; scratch layout k = u*4 + g
#define RDEPTH  4

// Scratch: x-part projections (+bias+theta folded), layout [t][b][u*4+g]
// Over-allocated by RDEPTH steps so the recurrence prefetch needs no bounds check.
__device__ float g_xproj[(T_STEPS + RDEPTH) * BATCH * NG];

// ---------------------------------------------------------------------------
// Kernel 1: fused 4-gate projection
// ---------------------------------------------------------------------------
#define TILE_ROWS    64
#define PROJ_THREADS 256

__global__ __launch_bounds__(PROJ_THREADS)
void proj_kernel(const float* __restrict__ x,
                 const float* __restrict__ Wf, const float* __restrict__ bf, const float* __restrict__ thf,
                 const float* __restrict__ Wi, const float* __restrict__ bi, const float* __restrict__ thi,
                 const float* __restrict__ Wu, const float* __restrict__ bu, const float* __restrict__ thu,
                 const float* __restrict__ Wo, const float* __restrict__ bo, const float* __restrict__ tho)
{
    __shared__ float xs[TILE_ROWS][132];
    __shared__ float ws[DIN][NG];          // ws[j][u*4+g]
    __shared__ float bt[NG];

    const int tid = threadIdx.x;
    const long rowBase = (long)blockIdx.x * TILE_ROWS;

    const float4* x4 = (const float4*)x + rowBase * (DIN / 4);
    #pragma unroll
    for (int i = tid; i < TILE_ROWS * (DIN / 4); i += PROJ_THREADS) {
        float4 v = x4[i];
        int row = i >> 5;
        int c4  = i & 31;
        *(float4*)&xs[row][c4 * 4] = v;
    }
    for (int i = tid; i < DIN * NG; i += PROJ_THREADS) {
        int j = i >> 4, k = i & 15;
        int u = k >> 2, g = k & 3;
        const float* W = (g == 0) ? Wf : (g == 1) ? Wi : (g == 2) ? Wu : Wo;
        ws[j][k] = W[j * 4 + u];
    }
    if (tid < NG) {
        int u = tid >> 2, g = tid & 3;
        const float* b  = (g == 0) ? bf  : (g == 1) ? bi  : (g == 2) ? bu  : bo;
        const float* th = (g == 0) ? thf : (g == 1) ? thi : (g == 2) ? thu : tho;
        bt[tid] = b[u] + th[u];
    }
    __syncthreads();

    const int r  = tid & (TILE_ROWS - 1);
    const int kg = tid >> 6;
    float a0 = 0.f, a1 = 0.f, a2 = 0.f, a3 = 0.f;

    #pragma unroll
    for (int jj = 0; jj < DIN / 4; jj++) {
        float4 xv = *(const float4*)&xs[r][jj * 4];
        float4 w0 = *(const float4*)&ws[jj * 4 + 0][kg * 4];
        float4 w1 = *(const float4*)&ws[jj * 4 + 1][kg * 4];
        float4 w2 = *(const float4*)&ws[jj * 4 + 2][kg * 4];
        float4 w3 = *(const float4*)&ws[jj * 4 + 3][kg * 4];
        a0 = fmaf(xv.x, w0.x, fmaf(xv.y, w1.x, fmaf(xv.z, w2.x, fmaf(xv.w, w3.x, a0))));
        a1 = fmaf(xv.x, w0.y, fmaf(xv.y, w1.y, fmaf(xv.z, w2.y, fmaf(xv.w, w3.y, a1))));
        a2 = fmaf(xv.x, w0.z, fmaf(xv.y, w1.z, fmaf(xv.z, w2.z, fmaf(xv.w, w3.z, a2))));
        a3 = fmaf(xv.x, w0.w, fmaf(xv.y, w1.w, fmaf(xv.z, w2.w, fmaf(xv.w, w3.w, a3))));
    }
    float4 o;
    o.x = a0 + bt[kg * 4 + 0];
    o.y = a1 + bt[kg * 4 + 1];
    o.z = a2 + bt[kg * 4 + 2];
    o.w = a3 + bt[kg * 4 + 3];
    *(float4*)&g_xproj[(rowBase + r) * NG + kg * 4] = o;
}

// ---------------------------------------------------------------------------
// Kernel 2: recurrence; 4 lanes per batch element (lane owns hidden unit u)
// ---------------------------------------------------------------------------
// sigmoid on [-1,1] via odd Taylor poly (err <= ~3e-6) -- FMA pipe only
__device__ __forceinline__ float sigp(float xv) {
    float x2 = xv * xv;
    float t = fmaf(x2, 2.135765e-5f, -2.1081349e-4f);
    t = fmaf(x2, t, 2.0833333e-3f);
    t = fmaf(x2, t, -2.0833333e-2f);
    t = fmaf(x2, t, 0.25f);
    return fmaf(xv, t, 0.5f);
}

// tanh via continued-fraction rational (Pade-class), err < ~1e-5 for |x| <= 2.2.
// tanh(x) = x*(10395 + 1260 t + 21 t^2) / (10395 + 4725 t + 210 t^2 + t^3), t = x^2
// Chain: t(4) -> den 3 fma(12) -> RCP(16) -> mul(4) -> mul(4) ~= 40 cyc, 1 MUFU.
__device__ __forceinline__ float tanh_cf(float xv) {
    float t = xv * xv;
    float num = fmaf(t, fmaf(t, 21.0f, 1260.0f), 10395.0f);
    float den = fmaf(t, fmaf(t, fmaf(t, 1.0f, 210.0f), 4725.0f), 10395.0f);
    return (xv * num) * __frcp_rn(den) ;
}
// NOTE: __frcp_rn is IEEE (multi-instr). Use fast approx divide instead:
__device__ __forceinline__ float tanh_cf_fast(float xv) {
    float t = xv * xv;
    float num = fmaf(t, fmaf(t, 21.0f, 1260.0f), 10395.0f);
    float den = fmaf(t, fmaf(t, fmaf(t, 1.0f, 210.0f), 4725.0f), 10395.0f);
    return __fdividef(xv * num, den);   // MUFU.RCP + mul
}

__global__ __launch_bounds__(32)
void recur_kernel(const float* __restrict__ Wf, const float* __restrict__ Wi,
                  const float* __restrict__ Wu, const float* __restrict__ Wo,
                  float* __restrict__ out)
{
    const int lane = threadIdx.x;
    const int u    = lane & 3;                       // hidden unit owned by this lane
    const int b    = blockIdx.x * 8 + (lane >> 2);   // batch element of this 4-lane group

    // Whl[m][g] = W_gate_g[(128+m)*4 + u]
    float Whl[4][4];
    #pragma unroll
    for (int m = 0; m < 4; m++) {
        Whl[m][0] = Wf[(128 + m) * 4 + u];
        Whl[m][1] = Wi[(128 + m) * 4 + u];
        Whl[m][2] = Wu[(128 + m) * 4 + u];
        Whl[m][3] = Wo[(128 + m) * 4 + u];
    }

    // hoisted scan predicates (branch-free SELs in the loop)
    const bool ge1 = (u >= 1);
    const bool ge2 = (u >= 2);
    const bool ge3 = (u >= 3);

    float h0 = 0.f, h1 = 0.f, h2 = 0.f, h3 = 0.f;
    float c  = 0.f;

    const float4* xp = (const float4*)g_xproj + ((size_t)b * 4 + u);
    float4 buf[RDEPTH];
    #pragma unroll
    for (int d = 0; d < RDEPTH; d++)
        buf[d] = xp[(size_t)d * (BATCH * 4)];

    #pragma unroll 4
    for (int t = 0; t < T_STEPS; t++) {
        const int slot = t & (RDEPTH - 1);
        float4 zx = buf[slot];
        buf[slot] = xp[(size_t)(t + RDEPTH) * (BATCH * 4)];

        // z_g = zx_g + h . Whl[:,g]  (tree form, depth ~12) then cos
        float q0, q1, q2, q3;
        {
            float a, bb;
            a  = fmaf(h1, Whl[1][0], fmaf(h0, Whl[0][0], zx.x));
            bb = fmaf(h3, Whl[3][0], h2 * Whl[2][0]);
            q0 = __cosf(a + bb);
            a  = fmaf(h1, Whl[1][1], fmaf(h0, Whl[0][1], zx.y));
            bb = fmaf(h3, Whl[3][1], h2 * Whl[2][1]);
            q1 = __cosf(a + bb);
            a  = fmaf(h1, Whl[1][2], fmaf(h0, Whl[0][2], zx.z));
            bb = fmaf(h3, Whl[3][2], h2 * Whl[2][2]);
            q2 = __cosf(a + bb);
            a  = fmaf(h1, Whl[1][3], fmaf(h0, Whl[0][3], zx.w));
            bb = fmaf(h3, Whl[3][3], h2 * Whl[2][3]);
            q3 = __cosf(a + bb);
        }

        // branch-free prefix product across the 4-lane group, per gate:
        // P_u = q_u * (u>=1 ? q(0) : 1) * (u>=2 ? q(1) : 1) * (u>=3 ? q(2) : 1)
        float P0, P1, P2, P3;
        {
            float a0s = __shfl_sync(0xffffffffu, q0, 0, 4);
            float a1s = __shfl_sync(0xffffffffu, q0, 1, 4);
            float a2s = __shfl_sync(0xffffffffu, q0, 2, 4);
            float b0s = __shfl_sync(0xffffffffu, q1, 0, 4);
            float b1s = __shfl_sync(0xffffffffu, q1, 1, 4);
            float b2s = __shfl_sync(0xffffffffu, q1, 2, 4);
            float c0s = __shfl_sync(0xffffffffu, q2, 0, 4);
            float c1s = __shfl_sync(0xffffffffu, q2, 1, 4);
            float c2s = __shfl_sync(0xffffffffu, q2, 2, 4);
            float d0s = __shfl_sync(0xffffffffu, q3, 0, 4);
            float d1s = __shfl_sync(0xffffffffu, q3, 1, 4);
            float d2s = __shfl_sync(0xffffffffu, q3, 2, 4);

            float m1 = ge1 ? a0s : 1.0f;
            float m2 = ge2 ? a1s : 1.0f;
            float m3 = ge3 ? a2s : 1.0f;
            P0 = (q0 * m1) * (m2 * m3);
            m1 = ge1 ? b0s : 1.0f;
            m2 = ge2 ? b1s : 1.0f;
            m3 = ge3 ? b2s : 1.0f;
            P1 = (q1 * m1) * (m2 * m3);
            m1 = ge1 ? c0s : 1.0f;
            m2 = ge2 ? c1s : 1.0f;
            m3 = ge3 ? c2s : 1.0f;
            P2 = (q2 * m1) * (m2 * m3);
            m1 = ge1 ? d0s : 1.0f;
            m2 = ge2 ? d1s : 1.0f;
            m3 = ge3 ? d2s : 1.0f;
            P3 = (q3 * m1) * (m2 * m3);
        }

        // activations + state update (local to this lane's unit)
        float f  = sigp(P0);
        float i  = sigp(P1);
        float gg = tanh_cf_fast(P2);
        float o  = sigp(P3);

        c = fmaf(f, c, i * gg);
        float hu = o * tanh_cf_fast(c);

        out[((size_t)t * BATCH + b) * 4 + u] = hu;

        // broadcast h within the 4-lane group (4 parallel shfls)
        h0 = __shfl_sync(0xffffffffu, hu, 0, 4);
        h1 = __shfl_sync(0xffffffffu, hu, 1, 4);
        h2 = __shfl_sync(0xffffffffu, hu, 2, 4);
        h3 = __shfl_sync(0xffffffffu, hu, 3, 4);
    }

    // hx, cx appended after outputs
    float hx = (u == 0) ? h0 : (u == 1) ? h1 : (u == 2) ? h2 : h3;
    out[(size_t)T_STEPS * BATCH * 4 + (size_t)b * 4 + u]                     = hx;
    out[(size_t)T_STEPS * BATCH * 4 + (size_t)BATCH * 4 + (size_t)b * 4 + u] = c;
}

// ---------------------------------------------------------------------------
extern "C" void kernel_launch(void* const* d_in, const int* in_sizes, int n_in,
                              void* d_out, int out_size)
{
    (void)in_sizes; (void)n_in; (void)out_size;
    const float* x   = (const float*)d_in[0];
    const float* Wf  = (const float*)d_in[1];
    const float* bf  = (const float*)d_in[2];
    const float* thf = (const float*)d_in[3];
    const float* Wi  = (const float*)d_in[4];
    const float* bi  = (const float*)d_in[5];
    const float* thi = (const float*)d_in[6];
    const float* Wu  = (const float*)d_in[7];
    const float* bu  = (const float*)d_in[8];
    const float* thu = (const float*)d_in[9];
    const float* Wo  = (const float*)d_in[10];
    const float* bo  = (const float*)d_in[11];
    const float* tho = (const float*)d_in[12];
    float* out = (float*)d_out;

    proj_kernel<<<(T_STEPS * BATCH) / TILE_ROWS, PROJ_THREADS>>>(
        x, Wf, bf, thf, Wi, bi, thi, Wu, bu, thu, Wo, bo, tho);
    recur_kernel<<<BATCH / 8, 32>>>(Wf, Wi, Wu, Wo, out);
}